// round 1
// baseline (speedup 1.0000x reference)
#include <cuda_runtime.h>

#define TH 32
#define TW 32
#define ZR 74   // 2*TH + 10 z-rows needed
#define ZC 74   // 2*TW + 10 z-cols needed
#define NI 24   // input rows/cols needed per tile
#define H_IN 128
#define W_IN 128
#define H_OUT 236
#define W_OUT 236
#define C_CH 256

__global__ __launch_bounds__(256) void afa_fused_kernel(
    const float* __restrict__ x, const float* __restrict__ bias,
    const float* __restrict__ kup, const float* __restrict__ kdn,
    float* __restrict__ out)
{
    // SMEM pipeline buffers
    __shared__ float sIN[NI][NI + 1];      // 24 x 25  input patch (+bias)
    __shared__ float sT1[NI][ZC + 2];      // 24 x 76  after horizontal 4x upsample
    __shared__ float sZ [ZR][ZC + 1];      // 74 x 75  after vertical upsample + lrelu
    __shared__ float sT3[ZR][TW];          // 74 x 32  after horizontal 2x downsample
    __shared__ float skup[24];
    __shared__ float skdn[12];

    const int tid = threadIdx.x;
    const int bz  = blockIdx.z;            // b*C + c
    const int ch  = bz & (C_CH - 1);
    const int y0  = blockIdx.y * TH;       // output tile origin
    const int x0  = blockIdx.x * TW;

    if (tid < 24)            skup[tid]      = kup[tid];
    else if (tid < 36)       skdn[tid - 24] = kdn[tid - 24];

    const float bv = bias[ch];
    // Input patch origin: derived from z-range [2*y0+15, 2*y0+88]
    const int IR0 = (y0 >> 1) + 1;
    const int IC0 = (x0 >> 1) + 1;
    const float* __restrict__ xp = x + (long long)bz * (H_IN * W_IN);

    // ---- Stage 1: load 24x24 input patch, add bias (clamped; clamped rows
    // feed only outputs beyond 236 which are never stored) ----
    for (int idx = tid; idx < NI * NI; idx += 256) {
        int r  = idx / NI, cc = idx % NI;
        int gr = min(IR0 + r,  H_IN - 1);
        int gc = min(IC0 + cc, W_IN - 1);
        sIN[r][cc] = xp[gr * W_IN + gc] + bv;
    }
    __syncthreads();

    // ---- Stage 2: horizontal 4x upsample (polyphase, 6 taps) ----
    // T1[n][c] = sum_j kup[4j + ((c+1)&3)] * IN[n][((c+25)>>2)-1 - j]
    for (int idx = tid; idx < NI * ZC; idx += 256) {
        int n  = idx / ZC, cc = idx % ZC;
        int mh = ((cc + 25) >> 2) - 1;
        int rh = (cc + 1) & 3;
        float acc = 0.f;
        #pragma unroll
        for (int j = 0; j < 6; j++)
            acc += skup[4 * j + rh] * sIN[n][mh - j];
        sT1[n][cc] = acc;
    }
    __syncthreads();

    // ---- Stage 3: vertical 4x upsample + leaky-relu * sqrt(2) ----
    for (int idx = tid; idx < ZR * ZC; idx += 256) {
        int i  = idx / ZC, cc = idx % ZC;
        int mr = ((i + 25) >> 2) - 1;
        int rv = (i + 1) & 3;
        float acc = 0.f;
        #pragma unroll
        for (int j = 0; j < 6; j++)
            acc += skup[4 * j + rv] * sT1[mr - j][cc];
        acc = (acc >= 0.f ? acc : 0.2f * acc) * 1.4142135623730951f;
        sZ[i][cc] = acc;
    }
    __syncthreads();

    // ---- Stage 4: horizontal 2x downsample (12 taps, stride 2) ----
    // local z col for output col xl, tap t: 2*xl + 11 - t  (in [0,73])
    for (int idx = tid; idx < ZR * TW; idx += 256) {
        int i  = idx / TW, xl = idx % TW;
        float acc = 0.f;
        #pragma unroll
        for (int t = 0; t < 12; t++)
            acc += skdn[t] * sZ[i][2 * xl + 11 - t];
        sT3[i][xl] = acc;
    }
    __syncthreads();

    // ---- Stage 5: vertical 2x downsample + store ----
    float* __restrict__ op = out + (long long)bz * (H_OUT * W_OUT);
    for (int idx = tid; idx < TH * TW; idx += 256) {
        int yl = idx / TW, xl = idx % TW;
        float acc = 0.f;
        #pragma unroll
        for (int t = 0; t < 12; t++)
            acc += skdn[t] * sT3[2 * yl + 11 - t][xl];
        int yg = y0 + yl, xg = x0 + xl;
        if (yg < H_OUT && xg < W_OUT)
            op[yg * W_OUT + xg] = acc;
    }
}

extern "C" void kernel_launch(void* const* d_in, const int* in_sizes, int n_in,
                              void* d_out, int out_size)
{
    const float* x   = (const float*)d_in[0];
    const float* b   = (const float*)d_in[1];
    const float* kup = (const float*)d_in[2];
    const float* kdn = (const float*)d_in[3];
    float* out = (float*)d_out;

    dim3 grid((W_OUT + TW - 1) / TW, (H_OUT + TH - 1) / TH, 4 * C_CH);  // 8 x 8 x 1024
    afa_fused_kernel<<<grid, 256>>>(x, b, kup, kdn, out);
}

// round 2
// speedup vs baseline: 3.2322x; 3.2322x over previous
#include <cuda_runtime.h>

#define TW 59
#define TH 32
#define ZC 128
#define NIR 24
#define NIC 38
#define HIN 128
#define WIN 128
#define HOUT 236
#define WOUT 236
#define SQRT2F 1.4142135623730951f

// Global-coordinate polyphase algebra (verified vs Round-1 passing kernel):
//   z col Zg:  phase=(Zg+2)&3, input cols ((Zg+10)>>2)-j, j=0..5
//   z row Ig:  phase=(Ig+2)&3, input rows ((Ig+10)>>2)-j
//   out col Xg reads z cols [2*Xg+15, 2*Xg+26]; same vertically.
// Tile: outputs [y0,y0+32) x [x0,x0+59); local z cols cc = Zg - (2*x0+15), 128 of them.

__global__ __launch_bounds__(256, 3) void afa_kernel(
    const float* __restrict__ x, const float* __restrict__ bias,
    const float* __restrict__ kup, const float* __restrict__ kdn,
    float* __restrict__ out)
{
    __shared__ float sIN[NIR][39];    // input patch (+bias), odd pitch
    __shared__ float sT1[NIR][129];   // after H-up; later aliased as sOut[32][61]
    __shared__ float sM [TH ][129];   // after fused V-up/lrelu/V-down
    __shared__ float sku[24];
    __shared__ float skd[12];

    const int tid = threadIdx.x;
    const int bz  = blockIdx.z;
    const int y0  = blockIdx.y * TH;
    const int x0  = blockIdx.x * TW;

    if (tid < 24)       sku[tid]      = kup[tid];
    else if (tid < 36)  skd[tid - 24] = kdn[tid - 24];

    const int Zbase = 2 * x0 + 15;            // global z col of local cc=0
    const int smin  = (Zbase + 10) >> 2;      // first input col group
    const int IC0   = smin - 5;               // input patch col origin
    const int IR0   = (y0 >> 1) + 1;          // input patch row origin
    const int off   = 4 * smin - 10 - Zbase;  // cc offset (-1 or -3)

    const float bv = bias[bz & 255];
    const float* __restrict__ xp = x + (long long)bz * (HIN * WIN);

    // ---- Stage 1: load 24x38 input patch + bias (clamped rows feed only
    // outputs >= 236 which are never stored) ----
    for (int idx = tid; idx < NIR * NIC; idx += 256) {
        int r  = idx / NIC, c = idx - r * NIC;
        int gr = min(IR0 + r, HIN - 1);
        int gc = min(IC0 + c, WIN - 1);
        sIN[r][c] = xp[gr * WIN + gc] + bv;
    }
    __syncthreads();

    float ku[24];
    #pragma unroll
    for (int i = 0; i < 24; i++) ku[i] = sku[i];
    float kd[12];
    #pragma unroll
    for (int i = 0; i < 12; i++) kd[i] = skd[i];

    // ---- Stage 2: horizontal 4x upsample, phase-blocked (6 LDS -> 4 cols) ----
    // group s = smin+si produces z cols Zg = 4s-10+q (q = phase), cc = 4*si+off+q
    for (int idx = tid; idx < 33 * 24; idx += 256) {
        int n  = idx % 24;       // row: consecutive lanes -> different rows (pitch 39, conflict-free)
        int si = idx / 24;
        float a0 = 0.f, a1 = 0.f, a2 = 0.f, a3 = 0.f;
        #pragma unroll
        for (int j = 0; j < 6; j++) {
            float v = sIN[n][si + 5 - j];
            a0 += ku[4 * j + 0] * v;
            a1 += ku[4 * j + 1] * v;
            a2 += ku[4 * j + 2] * v;
            a3 += ku[4 * j + 3] * v;
        }
        int cb = 4 * si + off;
        if ((unsigned)(cb + 0) < ZC) sT1[n][cb + 0] = a0;
        if ((unsigned)(cb + 1) < ZC) sT1[n][cb + 1] = a1;
        if ((unsigned)(cb + 2) < ZC) sT1[n][cb + 2] = a2;
        if ((unsigned)(cb + 3) < ZC) sT1[n][cb + 3] = a3;
    }
    __syncthreads();

    // ---- Stage 3 (fused, register-resident): vertical 4x up + lrelu*sqrt2 +
    // vertical 2x down. One column per thread, 16 output rows per thread. ----
    {
        const int cc = tid & 127;
        const int h  = tid >> 7;          // row half: outputs yl = 16h..16h+15
        float vin[16];
        #pragma unroll
        for (int r = 0; r < 16; r++) vin[r] = sT1[8 * h + r][cc];

        // rolling window of 12 full-res rows (thread-local z index ii = i - 32h;
        // phases/rows independent of h: phase=(ii+1)&3, reg=((ii+25)>>2)-1-j)
        float zw[12];
        #pragma unroll
        for (int ii = 0; ii < 10; ii++) {
            const int rv = (ii + 1) & 3, mr = ((ii + 25) >> 2) - 1;
            float a = 0.f;
            #pragma unroll
            for (int j = 0; j < 6; j++) a += ku[4 * j + rv] * vin[mr - j];
            zw[ii % 12] = (a >= 0.f ? a : 0.2f * a) * SQRT2F;
        }
        #pragma unroll
        for (int l = 0; l < 16; l++) {
            #pragma unroll
            for (int p = 0; p < 2; p++) {
                const int ii = 2 * l + 10 + p;
                const int rv = (ii + 1) & 3, mr = ((ii + 25) >> 2) - 1;
                float a = 0.f;
                #pragma unroll
                for (int j = 0; j < 6; j++) a += ku[4 * j + rv] * vin[mr - j];
                zw[ii % 12] = (a >= 0.f ? a : 0.2f * a) * SQRT2F;
            }
            float acc = 0.f;
            #pragma unroll
            for (int t = 0; t < 12; t++) acc += kd[t] * zw[(2 * l + 11 - t) % 12];
            sM[16 * h + l][cc] = acc;
        }
    }
    __syncthreads();

    // ---- Stage 4: horizontal 2x downsample, 4-wide blocked (18 LDS -> 4 outs) ----
    float (*sOut)[61] = (float (*)[61]) & sT1[0][0];   // reuse sT1 storage
    for (int idx = tid; idx < 15 * 32; idx += 256) {
        int g = idx >> 5, yl = idx & 31;   // lanes walk yl: pitch 129 -> conflict-free
        int c0 = 8 * g;
        float r[18];
        #pragma unroll
        for (int k = 0; k < 18; k++) r[k] = (c0 + k < ZC) ? sM[yl][c0 + k] : 0.f;
        #pragma unroll
        for (int q = 0; q < 4; q++) {
            int xl = 4 * g + q;
            if (xl < TW) {
                float acc = 0.f;
                #pragma unroll
                for (int t = 0; t < 12; t++) acc += kd[t] * r[2 * q + 11 - t];
                sOut[yl][xl] = acc;
            }
        }
    }
    __syncthreads();

    // ---- Stage 5: coalesced store ----
    float* __restrict__ op = out + (long long)bz * (HOUT * WOUT);
    for (int idx = tid; idx < TH * TW; idx += 256) {
        int yl = idx / TW, xl = idx - yl * TW;
        int yg = y0 + yl;
        if (yg < HOUT) op[yg * WOUT + x0 + xl] = sOut[yl][xl];
    }
}

extern "C" void kernel_launch(void* const* d_in, const int* in_sizes, int n_in,
                              void* d_out, int out_size)
{
    const float* x   = (const float*)d_in[0];
    const float* b   = (const float*)d_in[1];
    const float* kup = (const float*)d_in[2];
    const float* kdn = (const float*)d_in[3];
    float* out = (float*)d_out;

    dim3 grid(WOUT / TW, (HOUT + TH - 1) / TH, 4 * 256);   // 4 x 8 x 1024
    afa_kernel<<<grid, 256>>>(x, b, kup, kdn, out);
}

// round 3
// speedup vs baseline: 3.6879x; 1.1410x over previous
#include <cuda_runtime.h>

#define TW 59
#define TH 32
#define ZC 128
#define NIR 24
#define NIC 38
#define HIN 128
#define WIN 128
#define HOUT 236
#define WOUT 236
#define C1F 0.84852813742385702928f   // 0.6*sqrt(2)
#define C2F 0.56568542494923801952f   // 0.4*sqrt(2)

// Polyphase algebra (global coords, verified in R1/R2):
//   z col Zg: phase=(Zg+2)&3, input cols ((Zg+10)>>2)-j, j=0..5
//   out col Xg reads z cols [2*Xg+15, 2*Xg+26]; same vertically.
// Tile: outputs [y0,y0+32) x [x0,x0+59); local z col cc = Zg-(2*x0+15).

__global__ __launch_bounds__(256, 3) void afa_kernel(
    const float* __restrict__ x, const float* __restrict__ bias,
    const float* __restrict__ kup, const float* __restrict__ kdn,
    float* __restrict__ out)
{
    __shared__ float sIN[NIR][39];    // input patch (+bias)
    __shared__ float sT1[NIR][137];   // after H-up (stored at col+3); aliased later as sOut[32][61]
    __shared__ float sM [TH ][130];   // after fused V-up/lrelu/V-down (even pitch -> LDS.64)
    __shared__ float sku[24];
    __shared__ float skd[12];

    const int tid = threadIdx.x;
    const int bz  = blockIdx.z;
    const int y0  = blockIdx.y * TH;
    const int x0  = blockIdx.x * TW;

    if (tid < 24)       sku[tid]      = kup[tid];
    else if (tid < 36)  skd[tid - 24] = kdn[tid - 24];

    const int Zbase = 2 * x0 + 15;
    const int smin  = (Zbase + 10) >> 2;
    const int IC0   = smin - 5;
    const int IR0   = (y0 >> 1) + 1;
    const int off   = 4 * smin - 10 - Zbase;   // -1 or -3

    const float bv = bias[bz & 255];
    const float* __restrict__ xp = x + (long long)bz * (HIN * WIN);

    // ---- Stage 1: load 24x38 input patch + bias (no integer division) ----
    {
        const int c = tid & 31;
        #pragma unroll
        for (int r = tid >> 5; r < NIR; r += 8) {
            const int gr = min(IR0 + r, HIN - 1) * WIN;
            sIN[r][c] = xp[gr + min(IC0 + c, WIN - 1)] + bv;
            if (c < NIC - 32)
                sIN[r][c + 32] = xp[gr + min(IC0 + c + 32, WIN - 1)] + bv;
        }
    }
    __syncthreads();

    float ku[24];
    #pragma unroll
    for (int i = 0; i < 24; i++) ku[i] = sku[i];
    float kd[12];
    #pragma unroll
    for (int i = 0; i < 12; i++) kd[i] = skd[i];

    // ---- Stage 2: horizontal 4x upsample, phase-blocked, unconditional stores ----
    // group s=smin+si -> z cols cc = 4*si+off+q ; stored at [cc+3] in [0,135]
    for (int idx = tid; idx < 33 * 24; idx += 256) {
        int n  = idx % 24;            // lanes walk rows; pitch 39 conflict-free
        int si = idx / 24;
        float a0 = 0.f, a1 = 0.f, a2 = 0.f, a3 = 0.f;
        #pragma unroll
        for (int j = 0; j < 6; j++) {
            float v = sIN[n][si + 5 - j];
            a0 += ku[4 * j + 0] * v;
            a1 += ku[4 * j + 1] * v;
            a2 += ku[4 * j + 2] * v;
            a3 += ku[4 * j + 3] * v;
        }
        int cb = 4 * si + off + 3;    // in [0, 132]
        sT1[n][cb + 0] = a0;
        sT1[n][cb + 1] = a1;
        sT1[n][cb + 2] = a2;
        sT1[n][cb + 3] = a3;
    }
    __syncthreads();

    // ---- Stage 3 (register pipeline): V-up + lrelu*sqrt2 + V-down ----
    {
        const int cc = (tid & 127) + 3;    // +3 matches shifted sT1 storage
        const int h  = tid >> 7;           // outputs yl = 16h..16h+15
        float vin[16];
        #pragma unroll
        for (int r = 0; r < 16; r++) vin[r] = sT1[8 * h + r][cc];

        // z local index ii: phase=(ii+1)&3, src reg ((ii+25)>>2)-1-j
        float zw[12];
        #pragma unroll
        for (int ii = 0; ii < 10; ii++) {
            const int rv = (ii + 1) & 3, mr = ((ii + 25) >> 2) - 1;
            float a = 0.f;
            #pragma unroll
            for (int j = 0; j < 6; j++) a += ku[4 * j + rv] * vin[mr - j];
            zw[ii % 12] = fmaf(C2F, fabsf(a), C1F * a);   // lrelu*sqrt2, branch-free
        }
        #pragma unroll
        for (int l = 0; l < 16; l++) {
            #pragma unroll
            for (int p = 0; p < 2; p++) {
                const int ii = 2 * l + 10 + p;
                const int rv = (ii + 1) & 3, mr = ((ii + 25) >> 2) - 1;
                float a = 0.f;
                #pragma unroll
                for (int j = 0; j < 6; j++) a += ku[4 * j + rv] * vin[mr - j];
                zw[ii % 12] = fmaf(C2F, fabsf(a), C1F * a);
            }
            float acc = 0.f;
            #pragma unroll
            for (int t = 0; t < 12; t++) acc += kd[t] * zw[(2 * l + 11 - t) % 12];
            sM[16 * h + l][cc - 3] = acc;
        }
    }
    __syncthreads();

    // ---- Stage 4: horizontal 2x downsample, LDS.64 reads ----
    float (*sOut)[61] = (float (*)[61]) & sT1[0][0];   // alias sT1 storage
    for (int idx = tid; idx < 15 * 32; idx += 256) {
        int g = idx >> 5, yl = idx & 31;   // lanes walk yl: even pitch 130, conflict-free .64
        const float2* __restrict__ row2 =
            (const float2*)&sM[yl][8 * g];          // 8g even, pitch even -> aligned
        float r[18];
        #pragma unroll
        for (int k = 0; k < 9; k++) {
            float2 v = row2[k];
            r[2 * k] = v.x; r[2 * k + 1] = v.y;
        }
        #pragma unroll
        for (int q = 0; q < 4; q++) {
            int xl = 4 * g + q;
            if (xl < TW) {
                float acc = 0.f;
                #pragma unroll
                for (int t = 0; t < 12; t++) acc += kd[t] * r[2 * q + 11 - t];
                sOut[yl][xl] = acc;
            }
        }
    }
    __syncthreads();

    // ---- Stage 5: coalesced store ----
    float* __restrict__ op = out + (long long)bz * (HOUT * WOUT);
    for (int idx = tid; idx < TH * TW; idx += 256) {
        int yl = idx / TW, xl = idx - yl * TW;
        int yg = y0 + yl;
        if (yg < HOUT) op[yg * WOUT + x0 + xl] = sOut[yl][xl];
    }
}

extern "C" void kernel_launch(void* const* d_in, const int* in_sizes, int n_in,
                              void* d_out, int out_size)
{
    const float* x   = (const float*)d_in[0];
    const float* b   = (const float*)d_in[1];
    const float* kup = (const float*)d_in[2];
    const float* kdn = (const float*)d_in[3];
    float* out = (float*)d_out;

    dim3 grid(WOUT / TW, (HOUT + TH - 1) / TH, 4 * 256);   // 4 x 8 x 1024
    afa_kernel<<<grid, 256>>>(x, b, kup, kdn, out);
}